// round 4
// baseline (speedup 1.0000x reference)
#include <cuda_runtime.h>
#include <math.h>
#include <float.h>

#define N_NODES 100000
#define E_EDGES 1600000
#define E_TOT   (E_EDGES + N_NODES)
#define F_IN 64
#define H1   64
#define C2   32
#define NEG_SLOPE 0.2f
#define EPS_F 1e-16f
#define SCAN_B 1024
#define NB ((N_NODES + SCAN_B - 1) / SCAN_B)

// ---- static device scratch (allocation-free rule) ----
__device__ __align__(16) float g_h1[(size_t)N_NODES * H1];   // x@W1
__device__ __align__(16) float g_o1[(size_t)N_NODES * H1];   // relu(agg1)
__device__ __align__(16) float g_h2[(size_t)N_NODES * C2];   // o1@W2
__device__ float g_as[N_NODES];
__device__ float g_ad[N_NODES];
__device__ int   g_adj[E_TOT];     // CSR: src indices grouped by dst
__device__ int   g_dst[E_TOT];
__device__ int   g_srcbuf[E_TOT];
__device__ int   g_deg[N_NODES];
__device__ int   g_incl[N_NODES];  // inclusive prefix of deg
__device__ int   g_cur[N_NODES];   // scatter tickets
__device__ int   g_bsum[NB];
__device__ int   g_boff[NB];
__device__ int   g_is64;

// ---- detect whether edge_index is int64 or int32 (JAX x64-off downcast) ----
__global__ void k_detect(const void* __restrict__ ei, int E, int N) {
    if (threadIdx.x != 0 || blockIdx.x != 0) return;
    const long long* p = (const long long*)ei;
    int n = 2 * E < 256 ? 2 * E : 256;
    int ok = 1;
    for (int i = 0; i < n; i++) {
        long long v = p[i];
        if (v < 0 || v >= (long long)N) { ok = 0; break; }
    }
    g_is64 = ok;
}

// ---- zero counters ----
__global__ void k_zero(int N) {
    int i = blockIdx.x * blockDim.x + threadIdx.x;
    if (i < N) { g_deg[i] = 0; g_cur[i] = 0; }
}

// ---- build int32 edge lists + self loops; histogram deg[dst] ----
__global__ void k_build_edges(const void* __restrict__ ei, int E, int N) {
    int j = blockIdx.x * blockDim.x + threadIdx.x;
    int tot = E + N;
    if (j >= tot) return;
    int s, d;
    if (j < E) {
        if (g_is64) {
            const long long* p = (const long long*)ei;
            s = (int)p[j]; d = (int)p[(size_t)E + j];
        } else {
            const int* p = (const int*)ei;
            s = p[j]; d = p[E + j];
        }
    } else { s = j - E; d = j - E; }
    // clamp defensively (avoid wild writes even if detection is somehow wrong)
    s = s < 0 ? 0 : (s >= N ? N - 1 : s);
    d = d < 0 ? 0 : (d >= N ? N - 1 : d);
    g_srcbuf[j] = s;
    g_dst[j] = d;
    atomicAdd(&g_deg[d], 1);
}

// ---- scan step 1: per-block inclusive scan of deg ----
__global__ void k_scan1(int N) {
    __shared__ int sh[SCAN_B];
    int tid = threadIdx.x;
    int i = blockIdx.x * SCAN_B + tid;
    int v = (i < N) ? g_deg[i] : 0;
    sh[tid] = v;
    __syncthreads();
    #pragma unroll
    for (int off = 1; off < SCAN_B; off <<= 1) {
        int t = (tid >= off) ? sh[tid - off] : 0;
        __syncthreads();
        sh[tid] += t;
        __syncthreads();
    }
    if (i < N) g_incl[i] = sh[tid];
    if (tid == SCAN_B - 1) g_bsum[blockIdx.x] = sh[tid];
}

// ---- scan step 2: exclusive scan of block sums (tiny) ----
__global__ void k_scan2(int nb) {
    if (threadIdx.x == 0 && blockIdx.x == 0) {
        int run = 0;
        for (int b = 0; b < nb; b++) { int t = g_bsum[b]; g_boff[b] = run; run += t; }
    }
}

// ---- scan step 3: add block offsets ----
__global__ void k_scan3(int N) {
    int i = blockIdx.x * blockDim.x + threadIdx.x;
    if (i < N) g_incl[i] += g_boff[i / SCAN_B];
}

// ---- scatter src indices into CSR slots ----
__global__ void k_scatter(int Etot) {
    int j = blockIdx.x * blockDim.x + threadIdx.x;
    if (j >= Etot) return;
    int d = g_dst[j];
    int base = g_incl[d] - g_deg[d];
    int t = atomicAdd(&g_cur[d], 1);
    g_adj[base + t] = g_srcbuf[j];
}

// ---- layer1 GEMM: h1 = x @ W1 (64x64), fused alpha_src/alpha_dst dots ----
__global__ void k_gemm1(const float* __restrict__ x, const float* __restrict__ W,
                        const float* __restrict__ a_s, const float* __restrict__ a_d, int N) {
    __shared__ float Ws[F_IN * H1];   // 16 KB
    __shared__ float xs[8][F_IN];
    int tid = threadIdx.x;
    for (int i = tid; i < F_IN * H1; i += 256) Ws[i] = W[i];
    int warp = tid >> 5, lane = tid & 31;
    int node = blockIdx.x * 8 + warp;
    if (node < N) {
        xs[warp][lane]      = x[(size_t)node * F_IN + lane];
        xs[warp][lane + 32] = x[(size_t)node * F_IN + lane + 32];
    }
    __syncthreads();
    if (node >= N) return;
    float s0 = 0.f, s1 = 0.f;
    #pragma unroll
    for (int k = 0; k < F_IN; k++) {
        float xv = xs[warp][k];
        s0 = fmaf(xv, Ws[k * H1 + lane],      s0);
        s1 = fmaf(xv, Ws[k * H1 + lane + 32], s1);
    }
    g_h1[(size_t)node * H1 + lane]      = s0;
    g_h1[(size_t)node * H1 + lane + 32] = s1;
    float vs = s0 * a_s[lane] + s1 * a_s[lane + 32];
    float vd = s0 * a_d[lane] + s1 * a_d[lane + 32];
    #pragma unroll
    for (int o = 16; o > 0; o >>= 1) {
        vs += __shfl_xor_sync(0xffffffffu, vs, o);
        vd += __shfl_xor_sync(0xffffffffu, vd, o);
    }
    if (lane == 0) { g_as[node] = vs; g_ad[node] = vd; }
}

// ---- layer2 GEMM: h2 = o1 @ W2 (64x32), fused alpha dots ----
__global__ void k_gemm2(const float* __restrict__ W,
                        const float* __restrict__ a_s, const float* __restrict__ a_d, int N) {
    __shared__ float Ws[F_IN * C2];   // 8 KB
    __shared__ float xs[8][F_IN];
    int tid = threadIdx.x;
    for (int i = tid; i < F_IN * C2; i += 256) Ws[i] = W[i];
    int warp = tid >> 5, lane = tid & 31;
    int node = blockIdx.x * 8 + warp;
    if (node < N) {
        xs[warp][lane]      = g_o1[(size_t)node * F_IN + lane];
        xs[warp][lane + 32] = g_o1[(size_t)node * F_IN + lane + 32];
    }
    __syncthreads();
    if (node >= N) return;
    float s0 = 0.f;
    #pragma unroll
    for (int k = 0; k < F_IN; k++)
        s0 = fmaf(xs[warp][k], Ws[k * C2 + lane], s0);
    g_h2[(size_t)node * C2 + lane] = s0;
    float vs = s0 * a_s[lane];
    float vd = s0 * a_d[lane];
    #pragma unroll
    for (int o = 16; o > 0; o >>= 1) {
        vs += __shfl_xor_sync(0xffffffffu, vs, o);
        vd += __shfl_xor_sync(0xffffffffu, vd, o);
    }
    if (lane == 0) { g_as[node] = vs; g_ad[node] = vd; }
}

// ---- fused attention aggregation: one warp per destination node ----
// online softmax over incoming edges; no float atomics.
template<int CH, bool RELU>
__global__ void k_aggregate(const float* __restrict__ h, float* __restrict__ o,
                            const float* __restrict__ b, int N) {
    int gw = (blockIdx.x * blockDim.x + threadIdx.x) >> 5;
    int lane = threadIdx.x & 31;
    if (gw >= N) return;
    int end = g_incl[gw];
    int start = end - g_deg[gw];
    float adv = g_ad[gw];
    float m = -FLT_MAX, den = 0.f;
    float acc0 = 0.f, acc1 = 0.f;
    for (int p = start; p < end; p++) {
        int s = g_adj[p];                       // broadcast
        float v = g_as[s] + adv;                // broadcast
        float e = v > 0.f ? v : NEG_SLOPE * v;
        float newm = fmaxf(m, e);
        float scale = __expf(m - newm);
        float pw = __expf(e - newm);
        den = den * scale + pw;
        const float* hr = h + (size_t)s * CH;
        float h0 = hr[lane];
        acc0 = acc0 * scale + pw * h0;
        if (CH == 64) {
            float h1 = hr[lane + 32];
            acc1 = acc1 * scale + pw * h1;
        }
        m = newm;
    }
    float inv = 1.f / (den + EPS_F);
    float r0 = acc0 * inv + b[lane];
    if (RELU) r0 = fmaxf(r0, 0.f);
    o[(size_t)gw * CH + lane] = r0;
    if (CH == 64) {
        float r1 = acc1 * inv + b[lane + 32];
        if (RELU) r1 = fmaxf(r1, 0.f);
        o[(size_t)gw * CH + lane + 32] = r1;
    }
}

// ---- final log_softmax over 32 channels: 1 warp / node ----
__global__ void k_lsm(float* __restrict__ out, int N) {
    int gw = (blockIdx.x * blockDim.x + threadIdx.x) >> 5;
    int lane = threadIdx.x & 31;
    if (gw >= N) return;
    float v = out[(size_t)gw * C2 + lane];
    float mx = v;
    #pragma unroll
    for (int o = 16; o > 0; o >>= 1) mx = fmaxf(mx, __shfl_xor_sync(0xffffffffu, mx, o));
    float ex = __expf(v - mx);
    #pragma unroll
    for (int o = 16; o > 0; o >>= 1) ex += __shfl_xor_sync(0xffffffffu, ex, o);
    out[(size_t)gw * C2 + lane] = v - mx - logf(ex);
}

extern "C" void kernel_launch(void* const* d_in, const int* in_sizes, int n_in,
                              void* d_out, int out_size) {
    const float* x   = (const float*)d_in[0];
    const void*  ei  = d_in[1];
    const float* W1  = (const float*)d_in[2];
    const float* a1s = (const float*)d_in[3];
    const float* a1d = (const float*)d_in[4];
    const float* b1  = (const float*)d_in[5];
    const float* W2  = (const float*)d_in[6];
    const float* a2s = (const float*)d_in[7];
    const float* a2d = (const float*)d_in[8];
    const float* b2  = (const float*)d_in[9];
    float* out = (float*)d_out;

    int N = in_sizes[0] / F_IN;
    int E = in_sizes[1] / 2;
    int Etot = E + N;

    const int T = 256;
    float* p_o1; cudaGetSymbolAddress((void**)&p_o1, g_o1);
    float* p_h1; cudaGetSymbolAddress((void**)&p_h1, g_h1);
    float* p_h2; cudaGetSymbolAddress((void**)&p_h2, g_h2);

    // ---- CSR build ----
    k_detect<<<1, 32>>>(ei, E, N);
    k_zero<<<(N + T - 1) / T, T>>>(N);
    k_build_edges<<<(Etot + T - 1) / T, T>>>(ei, E, N);
    k_scan1<<<(N + SCAN_B - 1) / SCAN_B, SCAN_B>>>(N);
    k_scan2<<<1, 32>>>((N + SCAN_B - 1) / SCAN_B);
    k_scan3<<<(N + T - 1) / T, T>>>(N);
    k_scatter<<<(Etot + T - 1) / T, T>>>(Etot);

    // ---- layer 1: gemm + fused attention aggregation (+relu) ----
    k_gemm1<<<(N + 7) / 8, T>>>(x, W1, a1s, a1d, N);
    k_aggregate<H1, true><<<(N + 7) / 8, T>>>(p_h1, p_o1, b1, N);

    // ---- layer 2 ----
    k_gemm2<<<(N + 7) / 8, T>>>(W2, a2s, a2d, N);
    k_aggregate<C2, false><<<(N + 7) / 8, T>>>(p_h2, out, b2, N);

    // ---- log_softmax in-place on out ----
    k_lsm<<<(N * 32 + T - 1) / T, T>>>(out, N);
}

// round 5
// speedup vs baseline: 1.5697x; 1.5697x over previous
#include <cuda_runtime.h>
#include <math.h>
#include <float.h>

#define N_NODES 100000
#define E_EDGES 1600000
#define E_TOT   (E_EDGES + N_NODES)
#define F_IN 64
#define H1   64
#define C2   32
#define NEG_SLOPE 0.2f
#define EPS_F 1e-16f
#define SCAN_B 1024
#define NB ((N_NODES + SCAN_B - 1) / SCAN_B)
#define CAP 96   // smem-cached edges per node (max degree ~45 for Poisson(17))

// ---- static device scratch (allocation-free rule) ----
__device__ __align__(16) float g_h1[(size_t)N_NODES * H1];
__device__ __align__(16) float g_o1[(size_t)N_NODES * H1];
__device__ __align__(16) float g_h2[(size_t)N_NODES * C2];
__device__ float g_as[N_NODES];
__device__ float g_ad[N_NODES];
__device__ int   g_adj[E_TOT];
__device__ int   g_dst[E_TOT];
__device__ int   g_srcbuf[E_TOT];
__device__ int   g_deg[N_NODES];
__device__ int   g_incl[N_NODES];
__device__ int   g_cur[N_NODES];
__device__ int   g_bsum[NB];
__device__ int   g_boff[NB];
__device__ int   g_is64;

// ---- dtype sniff: parallel, one block ----
__global__ void k_detect(const long long* __restrict__ p, int E, int N) {
    __shared__ int bad;
    if (threadIdx.x == 0) bad = 0;
    __syncthreads();
    int n = 2 * E < 256 ? 2 * E : 256;
    if ((int)threadIdx.x < n) {
        long long v = p[threadIdx.x];
        if (v < 0 || v >= (long long)N) bad = 1;
    }
    __syncthreads();
    if (threadIdx.x == 0) g_is64 = bad ? 0 : 1;
}

__global__ void k_zero(int N) {
    int i = blockIdx.x * blockDim.x + threadIdx.x;
    if (i < N) { g_deg[i] = 0; g_cur[i] = 0; }
}

__global__ void k_build_edges(const void* __restrict__ ei, int E, int N) {
    int j = blockIdx.x * blockDim.x + threadIdx.x;
    int tot = E + N;
    if (j >= tot) return;
    int s, d;
    if (j < E) {
        if (g_is64) {
            const long long* p = (const long long*)ei;
            s = (int)p[j]; d = (int)p[(size_t)E + j];
        } else {
            const int* p = (const int*)ei;
            s = p[j]; d = p[E + j];
        }
    } else { s = j - E; d = j - E; }
    s = s < 0 ? 0 : (s >= N ? N - 1 : s);
    d = d < 0 ? 0 : (d >= N ? N - 1 : d);
    g_srcbuf[j] = s;
    g_dst[j] = d;
    atomicAdd(&g_deg[d], 1);
}

// ---- scan step 1: shuffle-based block inclusive scan ----
__global__ void k_scan1(int N) {
    int tid = threadIdx.x, lane = tid & 31, wid = tid >> 5;
    int i = blockIdx.x * SCAN_B + tid;
    int v = (i < N) ? g_deg[i] : 0;
    int x = v;
    #pragma unroll
    for (int o = 1; o < 32; o <<= 1) {
        int y = __shfl_up_sync(0xffffffffu, x, o);
        if (lane >= o) x += y;
    }
    __shared__ int ws[32];
    if (lane == 31) ws[wid] = x;
    __syncthreads();
    if (wid == 0) {
        int z = ws[lane];
        #pragma unroll
        for (int o = 1; o < 32; o <<= 1) {
            int q = __shfl_up_sync(0xffffffffu, z, o);
            if (lane >= o) z += q;
        }
        ws[lane] = z;
    }
    __syncthreads();
    if (wid > 0) x += ws[wid - 1];
    if (i < N) g_incl[i] = x;
    if (tid == SCAN_B - 1) g_bsum[blockIdx.x] = x;
}

// ---- scan step 2: parallel exclusive scan of <=128 block sums ----
__global__ void k_scan2(int nb) {
    int t = threadIdx.x, lane = t & 31, wid = t >> 5;
    int v = (t < nb) ? g_bsum[t] : 0;
    int x = v;
    #pragma unroll
    for (int o = 1; o < 32; o <<= 1) {
        int y = __shfl_up_sync(0xffffffffu, x, o);
        if (lane >= o) x += y;
    }
    __shared__ int ws[4];
    if (lane == 31) ws[wid] = x;
    __syncthreads();
    if (wid == 0) {
        int z = (lane < 4) ? ws[lane] : 0;
        #pragma unroll
        for (int o = 1; o < 4; o <<= 1) {
            int q = __shfl_up_sync(0xffffffffu, z, o);
            if (lane >= o) z += q;
        }
        if (lane < 4) ws[lane] = z;
    }
    __syncthreads();
    if (wid > 0) x += ws[wid - 1];
    if (t < nb) g_boff[t] = x - v;   // exclusive
}

__global__ void k_scan3(int N) {
    int i = blockIdx.x * blockDim.x + threadIdx.x;
    if (i < N) g_incl[i] += g_boff[i / SCAN_B];
}

__global__ void k_scatter(int Etot) {
    int j = blockIdx.x * blockDim.x + threadIdx.x;
    if (j >= Etot) return;
    int d = g_dst[j];
    int base = g_incl[d] - g_deg[d];
    int t = atomicAdd(&g_cur[d], 1);
    g_adj[base + t] = g_srcbuf[j];
}

// ---- layer1 GEMM: 64 nodes/block, 8 nodes/warp register tile ----
__global__ void k_gemm1(const float* __restrict__ x, const float* __restrict__ W,
                        const float* __restrict__ a_s, const float* __restrict__ a_d, int N) {
    __shared__ float Ws[F_IN * H1];      // 16 KB
    __shared__ float xs[64 * F_IN];      // 16 KB
    int tid = threadIdx.x;
    int base = blockIdx.x * 64;
    const float4* W4 = (const float4*)W;
    float4* Ws4 = (float4*)Ws;
    #pragma unroll
    for (int i = tid; i < F_IN * H1 / 4; i += 256) Ws4[i] = W4[i];
    int nvalid = N - base; if (nvalid > 64) nvalid = 64;
    const float4* x4 = (const float4*)(x + (size_t)base * F_IN);
    float4* xs4 = (float4*)xs;
    for (int i = tid; i < nvalid * (F_IN / 4); i += 256) xs4[i] = x4[i];
    __syncthreads();
    int w = tid >> 5, lane = tid & 31;
    float acc0[8], acc1[8];
    #pragma unroll
    for (int n = 0; n < 8; n++) { acc0[n] = 0.f; acc1[n] = 0.f; }
    #pragma unroll
    for (int k = 0; k < F_IN; k += 4) {
        float w00 = Ws[(k+0)*H1 + lane],      w01 = Ws[(k+1)*H1 + lane];
        float w02 = Ws[(k+2)*H1 + lane],      w03 = Ws[(k+3)*H1 + lane];
        float w10 = Ws[(k+0)*H1 + lane + 32], w11 = Ws[(k+1)*H1 + lane + 32];
        float w12 = Ws[(k+2)*H1 + lane + 32], w13 = Ws[(k+3)*H1 + lane + 32];
        #pragma unroll
        for (int n = 0; n < 8; n++) {
            float4 xv = *(const float4*)&xs[(w * 8 + n) * F_IN + k];
            acc0[n] = fmaf(xv.x, w00, fmaf(xv.y, w01, fmaf(xv.z, w02, fmaf(xv.w, w03, acc0[n]))));
            acc1[n] = fmaf(xv.x, w10, fmaf(xv.y, w11, fmaf(xv.z, w12, fmaf(xv.w, w13, acc1[n]))));
        }
    }
    float as0 = a_s[lane], as1 = a_s[lane + 32];
    float ad0 = a_d[lane], ad1 = a_d[lane + 32];
    #pragma unroll
    for (int n = 0; n < 8; n++) {
        int node = base + w * 8 + n;
        if (node >= N) break;
        g_h1[(size_t)node * H1 + lane]      = acc0[n];
        g_h1[(size_t)node * H1 + lane + 32] = acc1[n];
        float vs = acc0[n] * as0 + acc1[n] * as1;
        float vd = acc0[n] * ad0 + acc1[n] * ad1;
        #pragma unroll
        for (int o = 16; o > 0; o >>= 1) {
            vs += __shfl_xor_sync(0xffffffffu, vs, o);
            vd += __shfl_xor_sync(0xffffffffu, vd, o);
        }
        if (lane == 0) { g_as[node] = vs; g_ad[node] = vd; }
    }
}

// ---- layer2 GEMM: 64 nodes/block, 8 nodes/warp ----
__global__ void k_gemm2(const float* __restrict__ W,
                        const float* __restrict__ a_s, const float* __restrict__ a_d, int N) {
    __shared__ float Ws[F_IN * C2];      // 8 KB
    __shared__ float xs[64 * F_IN];      // 16 KB
    int tid = threadIdx.x;
    int base = blockIdx.x * 64;
    const float4* W4 = (const float4*)W;
    float4* Ws4 = (float4*)Ws;
    #pragma unroll
    for (int i = tid; i < F_IN * C2 / 4; i += 256) Ws4[i] = W4[i];
    int nvalid = N - base; if (nvalid > 64) nvalid = 64;
    const float4* x4 = (const float4*)(g_o1 + (size_t)base * F_IN);
    float4* xs4 = (float4*)xs;
    for (int i = tid; i < nvalid * (F_IN / 4); i += 256) xs4[i] = x4[i];
    __syncthreads();
    int w = tid >> 5, lane = tid & 31;
    float acc[8];
    #pragma unroll
    for (int n = 0; n < 8; n++) acc[n] = 0.f;
    #pragma unroll
    for (int k = 0; k < F_IN; k += 4) {
        float w0 = Ws[(k+0)*C2 + lane], w1 = Ws[(k+1)*C2 + lane];
        float w2 = Ws[(k+2)*C2 + lane], w3 = Ws[(k+3)*C2 + lane];
        #pragma unroll
        for (int n = 0; n < 8; n++) {
            float4 xv = *(const float4*)&xs[(w * 8 + n) * F_IN + k];
            acc[n] = fmaf(xv.x, w0, fmaf(xv.y, w1, fmaf(xv.z, w2, fmaf(xv.w, w3, acc[n]))));
        }
    }
    float as0 = a_s[lane], ad0 = a_d[lane];
    #pragma unroll
    for (int n = 0; n < 8; n++) {
        int node = base + w * 8 + n;
        if (node >= N) break;
        g_h2[(size_t)node * C2 + lane] = acc[n];
        float vs = acc[n] * as0;
        float vd = acc[n] * ad0;
        #pragma unroll
        for (int o = 16; o > 0; o >>= 1) {
            vs += __shfl_xor_sync(0xffffffffu, vs, o);
            vd += __shfl_xor_sync(0xffffffffu, vd, o);
        }
        if (lane == 0) { g_as[node] = vs; g_ad[node] = vd; }
    }
}

// ---- fused attention aggregation: warp/node, two-phase softmax ----
// Phase 1: lane-parallel max + denom (weights cached in smem).
// Phase 2: accumulation with only FFMA loop-carried dep (high MLP).
template<int CH, bool RELU, bool LSM>
__global__ void k_aggregate(const float* __restrict__ h, float* __restrict__ o,
                            const float* __restrict__ b, int N) {
    __shared__ float sw[8][CAP];
    __shared__ int   ss[8][CAP];
    int w = threadIdx.x >> 5, lane = threadIdx.x & 31;
    int gw = blockIdx.x * 8 + w;
    if (gw >= N) return;
    int end = g_incl[gw], deg = g_deg[gw], start = end - deg;
    int dc = deg < CAP ? deg : CAP;
    float adv = g_ad[gw];

    // phase 1a: max (and cache s, raw e)
    float m = -FLT_MAX;
    for (int i = lane; i < dc; i += 32) {
        int s = g_adj[start + i];
        float v = g_as[s] + adv;
        float e = v > 0.f ? v : NEG_SLOPE * v;
        ss[w][i] = s; sw[w][i] = e;
        m = fmaxf(m, e);
    }
    for (int i = dc + lane; i < deg; i += 32) {
        int s = g_adj[start + i];
        float v = g_as[s] + adv;
        float e = v > 0.f ? v : NEG_SLOPE * v;
        m = fmaxf(m, e);
    }
    #pragma unroll
    for (int o2 = 16; o2 > 0; o2 >>= 1) m = fmaxf(m, __shfl_xor_sync(0xffffffffu, m, o2));
    __syncwarp();

    // phase 1b: denom (convert cached e -> exp weight)
    float den = 0.f;
    for (int i = lane; i < dc; i += 32) {
        float ex = __expf(sw[w][i] - m);
        sw[w][i] = ex;
        den += ex;
    }
    for (int i = dc + lane; i < deg; i += 32) {
        int s = g_adj[start + i];
        float v = g_as[s] + adv;
        float e = v > 0.f ? v : NEG_SLOPE * v;
        den += __expf(e - m);
    }
    #pragma unroll
    for (int o2 = 16; o2 > 0; o2 >>= 1) den += __shfl_xor_sync(0xffffffffu, den, o2);
    float inv = 1.f / (den + EPS_F);
    __syncwarp();

    // phase 2: gather-accumulate (loads pipeline; acc dep = FFMA only)
    float acc0 = 0.f, acc1 = 0.f;
    for (int i = 0; i < dc; i++) {
        int s = ss[w][i];
        float wgt = sw[w][i];
        const float* hr = h + (size_t)s * CH;
        acc0 = fmaf(wgt, hr[lane], acc0);
        if (CH == 64) acc1 = fmaf(wgt, hr[lane + 32], acc1);
    }
    for (int i = dc; i < deg; i++) {   // overflow fallback (deg > CAP)
        int s = g_adj[start + i];
        float v = g_as[s] + adv;
        float e = v > 0.f ? v : NEG_SLOPE * v;
        float wgt = __expf(e - m);
        const float* hr = h + (size_t)s * CH;
        acc0 = fmaf(wgt, hr[lane], acc0);
        if (CH == 64) acc1 = fmaf(wgt, hr[lane + 32], acc1);
    }

    float r0 = acc0 * inv + b[lane];
    if (RELU) r0 = fmaxf(r0, 0.f);
    float r1 = 0.f;
    if (CH == 64) {
        r1 = acc1 * inv + b[lane + 32];
        if (RELU) r1 = fmaxf(r1, 0.f);
    }
    if (LSM) {   // CH==32: whole row lives in r0 across the warp
        float mx = r0;
        #pragma unroll
        for (int o2 = 16; o2 > 0; o2 >>= 1) mx = fmaxf(mx, __shfl_xor_sync(0xffffffffu, mx, o2));
        float ex = __expf(r0 - mx);
        #pragma unroll
        for (int o2 = 16; o2 > 0; o2 >>= 1) ex += __shfl_xor_sync(0xffffffffu, ex, o2);
        r0 = r0 - mx - logf(ex);
    }
    o[(size_t)gw * CH + lane] = r0;
    if (CH == 64) o[(size_t)gw * CH + lane + 32] = r1;
}

extern "C" void kernel_launch(void* const* d_in, const int* in_sizes, int n_in,
                              void* d_out, int out_size) {
    const float* x   = (const float*)d_in[0];
    const void*  ei  = d_in[1];
    const float* W1  = (const float*)d_in[2];
    const float* a1s = (const float*)d_in[3];
    const float* a1d = (const float*)d_in[4];
    const float* b1  = (const float*)d_in[5];
    const float* W2  = (const float*)d_in[6];
    const float* a2s = (const float*)d_in[7];
    const float* a2d = (const float*)d_in[8];
    const float* b2  = (const float*)d_in[9];
    float* out = (float*)d_out;

    int N = in_sizes[0] / F_IN;
    int E = in_sizes[1] / 2;
    int Etot = E + N;

    const int T = 256;
    float* p_o1; cudaGetSymbolAddress((void**)&p_o1, g_o1);
    float* p_h1; cudaGetSymbolAddress((void**)&p_h1, g_h1);
    float* p_h2; cudaGetSymbolAddress((void**)&p_h2, g_h2);

    // ---- CSR build ----
    k_detect<<<1, 256>>>((const long long*)ei, E, N);
    k_zero<<<(N + T - 1) / T, T>>>(N);
    k_build_edges<<<(Etot + T - 1) / T, T>>>(ei, E, N);
    k_scan1<<<(N + SCAN_B - 1) / SCAN_B, SCAN_B>>>(N);
    k_scan2<<<1, 128>>>((N + SCAN_B - 1) / SCAN_B);
    k_scan3<<<(N + T - 1) / T, T>>>(N);
    k_scatter<<<(Etot + T - 1) / T, T>>>(Etot);

    // ---- layer 1 ----
    k_gemm1<<<(N + 63) / 64, T>>>(x, W1, a1s, a1d, N);
    k_aggregate<H1, true, false><<<(N + 7) / 8, T>>>(p_h1, p_o1, b1, N);

    // ---- layer 2 (log_softmax fused into aggregation epilogue) ----
    k_gemm2<<<(N + 63) / 64, T>>>(W2, a2s, a2d, N);
    k_aggregate<C2, false, true><<<(N + 7) / 8, T>>>(p_h2, out, b2, N);
}

// round 6
// speedup vs baseline: 1.6487x; 1.0504x over previous
#include <cuda_runtime.h>
#include <math.h>
#include <float.h>

#define N_NODES 100000
#define E_EDGES 1600000
#define E_TOT   (E_EDGES + N_NODES)
#define F_IN 64
#define H1   64
#define C2   32
#define NEG_SLOPE 0.2f
#define EPS_F 1e-16f
#define SCAN_B 1024
#define NB ((N_NODES + SCAN_B - 1) / SCAN_B)
#define CAP 96

// ---- static device scratch ----
__device__ __align__(16) float2 g_h1p[(size_t)N_NODES * 32];   // pair layout: slot l = cols (l, l+32)
__device__ __align__(16) float  g_o1[(size_t)N_NODES * H1];
__device__ __align__(16) float  g_h2[(size_t)N_NODES * C2];
__device__ float g_as[N_NODES];
__device__ float g_ad[N_NODES];
__device__ int   g_adj[E_TOT];
__device__ int   g_deg[N_NODES];
__device__ int   g_incl[N_NODES];
__device__ int   g_cur[N_NODES];
__device__ int   g_bsum[NB];
__device__ int   g_boff[NB];
__device__ int   g_is64;

// ---- dtype sniff ----
__global__ void k_detect(const long long* __restrict__ p, int E, int N) {
    __shared__ int bad;
    if (threadIdx.x == 0) bad = 0;
    __syncthreads();
    int n = 2 * E < 256 ? 2 * E : 256;
    if ((int)threadIdx.x < n) {
        long long v = p[threadIdx.x];
        if (v < 0 || v >= (long long)N) bad = 1;
    }
    __syncthreads();
    if (threadIdx.x == 0) g_is64 = bad ? 0 : 1;
}

__global__ void k_zero(int N) {
    int i = blockIdx.x * blockDim.x + threadIdx.x;
    if (i < N) { g_deg[i] = 0; g_cur[i] = 0; }
}

__device__ __forceinline__ void decode_edge(const void* ei, int E, int N, int j,
                                            int& s, int& d) {
    if (j < E) {
        if (g_is64) {
            const long long* p = (const long long*)ei;
            s = (int)p[j]; d = (int)p[(size_t)E + j];
        } else {
            const int* p = (const int*)ei;
            s = p[j]; d = p[E + j];
        }
    } else { s = j - E; d = j - E; }
    s = s < 0 ? 0 : (s >= N ? N - 1 : s);
    d = d < 0 ? 0 : (d >= N ? N - 1 : d);
}

// ---- histogram deg[dst] ----
__global__ void k_build_edges(const void* __restrict__ ei, int E, int N) {
    int j = blockIdx.x * blockDim.x + threadIdx.x;
    if (j >= E + N) return;
    int s, d;
    decode_edge(ei, E, N, j, s, d);
    atomicAdd(&g_deg[d], 1);
}

// ---- scan step 1: shuffle-based block inclusive scan ----
__global__ void k_scan1(int N) {
    int tid = threadIdx.x, lane = tid & 31, wid = tid >> 5;
    int i = blockIdx.x * SCAN_B + tid;
    int v = (i < N) ? g_deg[i] : 0;
    int x = v;
    #pragma unroll
    for (int o = 1; o < 32; o <<= 1) {
        int y = __shfl_up_sync(0xffffffffu, x, o);
        if (lane >= o) x += y;
    }
    __shared__ int ws[32];
    if (lane == 31) ws[wid] = x;
    __syncthreads();
    if (wid == 0) {
        int z = ws[lane];
        #pragma unroll
        for (int o = 1; o < 32; o <<= 1) {
            int q = __shfl_up_sync(0xffffffffu, z, o);
            if (lane >= o) z += q;
        }
        ws[lane] = z;
    }
    __syncthreads();
    if (wid > 0) x += ws[wid - 1];
    if (i < N) g_incl[i] = x;
    if (tid == SCAN_B - 1) g_bsum[blockIdx.x] = x;
}

// ---- scan step 2: exclusive scan of <=128 block sums ----
__global__ void k_scan2(int nb) {
    int t = threadIdx.x, lane = t & 31, wid = t >> 5;
    int v = (t < nb) ? g_bsum[t] : 0;
    int x = v;
    #pragma unroll
    for (int o = 1; o < 32; o <<= 1) {
        int y = __shfl_up_sync(0xffffffffu, x, o);
        if (lane >= o) x += y;
    }
    __shared__ int ws[4];
    if (lane == 31) ws[wid] = x;
    __syncthreads();
    if (wid == 0) {
        int z = (lane < 4) ? ws[lane] : 0;
        #pragma unroll
        for (int o = 1; o < 4; o <<= 1) {
            int q = __shfl_up_sync(0xffffffffu, z, o);
            if (lane >= o) z += q;
        }
        if (lane < 4) ws[lane] = z;
    }
    __syncthreads();
    if (wid > 0) x += ws[wid - 1];
    if (t < nb) g_boff[t] = x - v;
}

__global__ void k_scan3(int N) {
    int i = blockIdx.x * blockDim.x + threadIdx.x;
    if (i < N) g_incl[i] += g_boff[i / SCAN_B];
}

// ---- scatter src indices into CSR slots (re-decodes ei) ----
__global__ void k_scatter(const void* __restrict__ ei, int E, int N) {
    int j = blockIdx.x * blockDim.x + threadIdx.x;
    if (j >= E + N) return;
    int s, d;
    decode_edge(ei, E, N, j, s, d);
    int base = g_incl[d] - g_deg[d];
    int t = atomicAdd(&g_cur[d], 1);
    g_adj[base + t] = s;
}

// ---- layer1 GEMM: 64 nodes/block, 8 nodes/warp; h1 in pair layout ----
__global__ void k_gemm1(const float* __restrict__ x, const float* __restrict__ W,
                        const float* __restrict__ a_s, const float* __restrict__ a_d, int N) {
    __shared__ float Ws[F_IN * H1];
    __shared__ float xs[64 * F_IN];
    int tid = threadIdx.x;
    int base = blockIdx.x * 64;
    const float4* W4 = (const float4*)W;
    float4* Ws4 = (float4*)Ws;
    #pragma unroll
    for (int i = tid; i < F_IN * H1 / 4; i += 256) Ws4[i] = W4[i];
    int nvalid = N - base; if (nvalid > 64) nvalid = 64;
    const float4* x4 = (const float4*)(x + (size_t)base * F_IN);
    float4* xs4 = (float4*)xs;
    for (int i = tid; i < nvalid * (F_IN / 4); i += 256) xs4[i] = x4[i];
    __syncthreads();
    int w = tid >> 5, lane = tid & 31;
    float acc0[8], acc1[8];
    #pragma unroll
    for (int n = 0; n < 8; n++) { acc0[n] = 0.f; acc1[n] = 0.f; }
    #pragma unroll
    for (int k = 0; k < F_IN; k += 4) {
        float w00 = Ws[(k+0)*H1 + lane],      w01 = Ws[(k+1)*H1 + lane];
        float w02 = Ws[(k+2)*H1 + lane],      w03 = Ws[(k+3)*H1 + lane];
        float w10 = Ws[(k+0)*H1 + lane + 32], w11 = Ws[(k+1)*H1 + lane + 32];
        float w12 = Ws[(k+2)*H1 + lane + 32], w13 = Ws[(k+3)*H1 + lane + 32];
        #pragma unroll
        for (int n = 0; n < 8; n++) {
            float4 xv = *(const float4*)&xs[(w * 8 + n) * F_IN + k];
            acc0[n] = fmaf(xv.x, w00, fmaf(xv.y, w01, fmaf(xv.z, w02, fmaf(xv.w, w03, acc0[n]))));
            acc1[n] = fmaf(xv.x, w10, fmaf(xv.y, w11, fmaf(xv.z, w12, fmaf(xv.w, w13, acc1[n]))));
        }
    }
    float as0 = a_s[lane], as1 = a_s[lane + 32];
    float ad0 = a_d[lane], ad1 = a_d[lane + 32];
    #pragma unroll
    for (int n = 0; n < 8; n++) {
        int node = base + w * 8 + n;
        if (node >= N) break;
        g_h1p[(size_t)node * 32 + lane] = make_float2(acc0[n], acc1[n]);
        float vs = acc0[n] * as0 + acc1[n] * as1;
        float vd = acc0[n] * ad0 + acc1[n] * ad1;
        #pragma unroll
        for (int o = 16; o > 0; o >>= 1) {
            vs += __shfl_xor_sync(0xffffffffu, vs, o);
            vd += __shfl_xor_sync(0xffffffffu, vd, o);
        }
        if (lane == 0) { g_as[node] = vs; g_ad[node] = vd; }
    }
}

// ---- layer2 GEMM: 64 nodes/block, 8 nodes/warp ----
__global__ void k_gemm2(const float* __restrict__ W,
                        const float* __restrict__ a_s, const float* __restrict__ a_d, int N) {
    __shared__ float Ws[F_IN * C2];
    __shared__ float xs[64 * F_IN];
    int tid = threadIdx.x;
    int base = blockIdx.x * 64;
    const float4* W4 = (const float4*)W;
    float4* Ws4 = (float4*)Ws;
    #pragma unroll
    for (int i = tid; i < F_IN * C2 / 4; i += 256) Ws4[i] = W4[i];
    int nvalid = N - base; if (nvalid > 64) nvalid = 64;
    const float4* x4 = (const float4*)(g_o1 + (size_t)base * F_IN);
    float4* xs4 = (float4*)xs;
    for (int i = tid; i < nvalid * (F_IN / 4); i += 256) xs4[i] = x4[i];
    __syncthreads();
    int w = tid >> 5, lane = tid & 31;
    float acc[8];
    #pragma unroll
    for (int n = 0; n < 8; n++) acc[n] = 0.f;
    #pragma unroll
    for (int k = 0; k < F_IN; k += 4) {
        float w0 = Ws[(k+0)*C2 + lane], w1 = Ws[(k+1)*C2 + lane];
        float w2 = Ws[(k+2)*C2 + lane], w3 = Ws[(k+3)*C2 + lane];
        #pragma unroll
        for (int n = 0; n < 8; n++) {
            float4 xv = *(const float4*)&xs[(w * 8 + n) * F_IN + k];
            acc[n] = fmaf(xv.x, w0, fmaf(xv.y, w1, fmaf(xv.z, w2, fmaf(xv.w, w3, acc[n]))));
        }
    }
    float as0 = a_s[lane], ad0 = a_d[lane];
    #pragma unroll
    for (int n = 0; n < 8; n++) {
        int node = base + w * 8 + n;
        if (node >= N) break;
        g_h2[(size_t)node * C2 + lane] = acc[n];
        float vs = acc[n] * as0;
        float vd = acc[n] * ad0;
        #pragma unroll
        for (int o = 16; o > 0; o >>= 1) {
            vs += __shfl_xor_sync(0xffffffffu, vs, o);
            vd += __shfl_xor_sync(0xffffffffu, vd, o);
        }
        if (lane == 0) { g_as[node] = vs; g_ad[node] = vd; }
    }
}

// ---- layer1 aggregation: warp/node, two-phase softmax, float2 gathers ----
__global__ void k_aggregate1(float* __restrict__ o, const float* __restrict__ b, int N) {
    __shared__ float sw[8][CAP];
    __shared__ int   ss[8][CAP];
    int w = threadIdx.x >> 5, lane = threadIdx.x & 31;
    int gw = blockIdx.x * 8 + w;
    if (gw >= N) return;
    int end = g_incl[gw], deg = g_deg[gw], start = end - deg;
    int dc = deg < CAP ? deg : CAP;
    float adv = g_ad[gw];

    float m = -FLT_MAX;
    for (int i = lane; i < dc; i += 32) {
        int s = g_adj[start + i];
        float v = g_as[s] + adv;
        float e = v > 0.f ? v : NEG_SLOPE * v;
        ss[w][i] = s; sw[w][i] = e;
        m = fmaxf(m, e);
    }
    for (int i = dc + lane; i < deg; i += 32) {
        int s = g_adj[start + i];
        float v = g_as[s] + adv;
        float e = v > 0.f ? v : NEG_SLOPE * v;
        m = fmaxf(m, e);
    }
    #pragma unroll
    for (int o2 = 16; o2 > 0; o2 >>= 1) m = fmaxf(m, __shfl_xor_sync(0xffffffffu, m, o2));
    __syncwarp();

    float den = 0.f;
    for (int i = lane; i < dc; i += 32) {
        float ex = __expf(sw[w][i] - m);
        sw[w][i] = ex;
        den += ex;
    }
    for (int i = dc + lane; i < deg; i += 32) {
        int s = g_adj[start + i];
        float v = g_as[s] + adv;
        float e = v > 0.f ? v : NEG_SLOPE * v;
        den += __expf(e - m);
    }
    #pragma unroll
    for (int o2 = 16; o2 > 0; o2 >>= 1) den += __shfl_xor_sync(0xffffffffu, den, o2);
    float inv = 1.f / (den + EPS_F);
    __syncwarp();

    float acc0 = 0.f, acc1 = 0.f;
    for (int i = 0; i < dc; i++) {
        int s = ss[w][i];
        float wgt = sw[w][i];
        float2 hv = g_h1p[(size_t)s * 32 + lane];   // one LDG.64: cols (lane, lane+32)
        acc0 = fmaf(wgt, hv.x, acc0);
        acc1 = fmaf(wgt, hv.y, acc1);
    }
    for (int i = dc; i < deg; i++) {
        int s = g_adj[start + i];
        float v = g_as[s] + adv;
        float e = v > 0.f ? v : NEG_SLOPE * v;
        float wgt = __expf(e - m);
        float2 hv = g_h1p[(size_t)s * 32 + lane];
        acc0 = fmaf(wgt, hv.x, acc0);
        acc1 = fmaf(wgt, hv.y, acc1);
    }

    float r0 = fmaxf(acc0 * inv + b[lane], 0.f);
    float r1 = fmaxf(acc1 * inv + b[lane + 32], 0.f);
    o[(size_t)gw * H1 + lane]      = r0;
    o[(size_t)gw * H1 + lane + 32] = r1;
}

// ---- layer2 aggregation + fused log_softmax ----
__global__ void k_aggregate2(const float* __restrict__ h, float* __restrict__ o,
                             const float* __restrict__ b, int N) {
    __shared__ float sw[8][CAP];
    __shared__ int   ss[8][CAP];
    int w = threadIdx.x >> 5, lane = threadIdx.x & 31;
    int gw = blockIdx.x * 8 + w;
    if (gw >= N) return;
    int end = g_incl[gw], deg = g_deg[gw], start = end - deg;
    int dc = deg < CAP ? deg : CAP;
    float adv = g_ad[gw];

    float m = -FLT_MAX;
    for (int i = lane; i < dc; i += 32) {
        int s = g_adj[start + i];
        float v = g_as[s] + adv;
        float e = v > 0.f ? v : NEG_SLOPE * v;
        ss[w][i] = s; sw[w][i] = e;
        m = fmaxf(m, e);
    }
    for (int i = dc + lane; i < deg; i += 32) {
        int s = g_adj[start + i];
        float v = g_as[s] + adv;
        float e = v > 0.f ? v : NEG_SLOPE * v;
        m = fmaxf(m, e);
    }
    #pragma unroll
    for (int o2 = 16; o2 > 0; o2 >>= 1) m = fmaxf(m, __shfl_xor_sync(0xffffffffu, m, o2));
    __syncwarp();

    float den = 0.f;
    for (int i = lane; i < dc; i += 32) {
        float ex = __expf(sw[w][i] - m);
        sw[w][i] = ex;
        den += ex;
    }
    for (int i = dc + lane; i < deg; i += 32) {
        int s = g_adj[start + i];
        float v = g_as[s] + adv;
        float e = v > 0.f ? v : NEG_SLOPE * v;
        den += __expf(e - m);
    }
    #pragma unroll
    for (int o2 = 16; o2 > 0; o2 >>= 1) den += __shfl_xor_sync(0xffffffffu, den, o2);
    float inv = 1.f / (den + EPS_F);
    __syncwarp();

    float acc0 = 0.f;
    for (int i = 0; i < dc; i++) {
        int s = ss[w][i];
        float wgt = sw[w][i];
        acc0 = fmaf(wgt, h[(size_t)s * C2 + lane], acc0);
    }
    for (int i = dc; i < deg; i++) {
        int s = g_adj[start + i];
        float v = g_as[s] + adv;
        float e = v > 0.f ? v : NEG_SLOPE * v;
        float wgt = __expf(e - m);
        acc0 = fmaf(wgt, h[(size_t)s * C2 + lane], acc0);
    }

    float r0 = acc0 * inv + b[lane];
    float mx = r0;
    #pragma unroll
    for (int o2 = 16; o2 > 0; o2 >>= 1) mx = fmaxf(mx, __shfl_xor_sync(0xffffffffu, mx, o2));
    float ex = __expf(r0 - mx);
    #pragma unroll
    for (int o2 = 16; o2 > 0; o2 >>= 1) ex += __shfl_xor_sync(0xffffffffu, ex, o2);
    r0 = r0 - mx - logf(ex);
    o[(size_t)gw * C2 + lane] = r0;
}

extern "C" void kernel_launch(void* const* d_in, const int* in_sizes, int n_in,
                              void* d_out, int out_size) {
    const float* x   = (const float*)d_in[0];
    const void*  ei  = d_in[1];
    const float* W1  = (const float*)d_in[2];
    const float* a1s = (const float*)d_in[3];
    const float* a1d = (const float*)d_in[4];
    const float* b1  = (const float*)d_in[5];
    const float* W2  = (const float*)d_in[6];
    const float* a2s = (const float*)d_in[7];
    const float* a2d = (const float*)d_in[8];
    const float* b2  = (const float*)d_in[9];
    float* out = (float*)d_out;

    int N = in_sizes[0] / F_IN;
    int E = in_sizes[1] / 2;
    int Etot = E + N;

    const int T = 256;
    float* p_o1; cudaGetSymbolAddress((void**)&p_o1, g_o1);
    float* p_h2; cudaGetSymbolAddress((void**)&p_h2, g_h2);

    // ---- CSR build ----
    k_detect<<<1, 256>>>((const long long*)ei, E, N);
    k_zero<<<(N + T - 1) / T, T>>>(N);
    k_build_edges<<<(Etot + T - 1) / T, T>>>(ei, E, N);
    k_scan1<<<(N + SCAN_B - 1) / SCAN_B, SCAN_B>>>(N);
    k_scan2<<<1, 128>>>((N + SCAN_B - 1) / SCAN_B);
    k_scan3<<<(N + T - 1) / T, T>>>(N);
    k_scatter<<<(Etot + T - 1) / T, T>>>(ei, E, N);

    // ---- layer 1 ----
    k_gemm1<<<(N + 63) / 64, T>>>(x, W1, a1s, a1d, N);
    k_aggregate1<<<(N + 7) / 8, T>>>(p_o1, b1, N);

    // ---- layer 2 (log_softmax fused) ----
    k_gemm2<<<(N + 63) / 64, T>>>(W2, a2s, a2d, N);
    k_aggregate2<<<(N + 7) / 8, T>>>(p_h2, out, b2, N);
}